// round 7
// baseline (speedup 1.0000x reference)
#include <cuda_runtime.h>
#include <math.h>
#include <float.h>

#define FULLMASK 0xFFFFFFFFu

constexpr int Bb   = 8;
constexpr int Seq  = 2048;
constexpr int Dd   = 1024;
constexpr int Ee   = 64;
constexpr int Mtot = Bb * Seq;          // 16384 tokens

constexpr int ROWBUF = 4100;            // 4098 + pad (scan scratch per row)

// scratch (no cudaMalloc allowed)
__device__ float g_nrm[Mtot];
__device__ float g_xT[(size_t)Bb * Dd * Seq];   // [b*D+d][t]; later overwritten with router_input
__device__ float g_z[(size_t)Mtot * Ee];        // logits

// packed fp32x2 FMA (sm_100+)
#define FMA2(c, a, b) asm("fma.rn.f32x2 %0, %1, %2, %0;" : "+l"(c) : "l"(a), "l"(b))

// ---------------- Kernel A: per-token norms ----------------
__global__ __launch_bounds__(256) void norm_kernel(const float* __restrict__ x)
{
    const int warp = (blockIdx.x * blockDim.x + threadIdx.x) >> 5;
    const int lane = threadIdx.x & 31;
    if (warp >= Mtot) return;
    const float4* px = (const float4*)(x + (size_t)warp * Dd);
    float s0 = 0.f, s1 = 0.f, s2 = 0.f, s3 = 0.f;
#pragma unroll
    for (int j = 0; j < 8; ++j) {
        const float4 v = px[lane + 32 * j];
        s0 += v.x * v.x;  s1 += v.y * v.y;
        s2 += v.z * v.z;  s3 += v.w * v.w;
    }
    float s = (s0 + s1) + (s2 + s3);
#pragma unroll
    for (int o = 16; o; o >>= 1) s += __shfl_xor_sync(FULLMASK, s, o);
    if (lane == 0) g_nrm[warp] = fmaxf(__fsqrt_rn(s), 1e-8f);
}

// ---------------- Kernel B1: transpose + normalize (IEEE division) ----------------
__global__ void transpose_norm_kernel(const float* __restrict__ x)
{
    __shared__ float tile[32][33];
    const int b  = blockIdx.z;
    const int t0 = blockIdx.x * 32;
    const int d0 = blockIdx.y * 32;
    const int tx = threadIdx.x, ty = threadIdx.y;

#pragma unroll
    for (int i = 0; i < 4; ++i) {
        const int t = t0 + ty + i * 8;
        tile[ty + i * 8][tx] = x[((size_t)b * Seq + t) * Dd + d0 + tx];
    }
    __syncthreads();
    const float rn = g_nrm[b * Seq + t0 + tx];
#pragma unroll
    for (int i = 0; i < 4; ++i) {
        const int d = d0 + ty + i * 8;
        g_xT[((size_t)b * Dd + d) * Seq + t0 + tx] = __fdiv_rn(tile[tx][ty + i * 8], rn);
    }
}

// ---------------- Kernel B2: emulate jax associative_scan cumsum + window ----------------
// Per (b,d) row: padded = [x0, x0, x0..x_{S-1}] (len 2050), C = inclusive Blelloch scan,
// router_input[s] = (C[s+2] - (s>=1 ? C[s-1] : 0)) / 3, written in place over g_xT.
__global__ __launch_bounds__(256) void scan_kernel()
{
    // level geometry for padded length 2050 (local constexpr: visible in device code,
    // fully folded since all indexing comes from the unrolled L loop)
    constexpr int NLV = 12;
    constexpr int LLEN[NLV] = {2050,1025,512,256,128,64,32,16,8,4,2,1};
    constexpr int LOFF[NLV] = {0,2050,3075,3587,3843,3971,4035,4067,4083,4091,4095,4097};

    __shared__ float sm[2 * ROWBUF];
    const int tid = threadIdx.x;
    const size_t grow0 = (size_t)blockIdx.x * 2;

    // load 2 rows (t-contiguous, coalesced)
    for (int idx = tid; idx < 2 * Seq; idx += 256) {
        const int r = idx >> 11, t = idx & (Seq - 1);
        sm[r * ROWBUF + 2 + t] = g_xT[(grow0 + r) * Seq + t];
    }
    __syncthreads();
    if (tid < 2) {
        const float v = sm[tid * ROWBUF + 2];
        sm[tid * ROWBUF + 0] = v;
        sm[tid * ROWBUF + 1] = v;
    }
    __syncthreads();

    // up-sweep: pairwise reductions, level by level
#pragma unroll
    for (int L = 0; L < NLV - 1; ++L) {
        const int np = LLEN[L + 1];
        for (int idx = tid; idx < 2 * np; idx += 256) {
            const int r = (idx < np) ? 0 : 1;
            const int i = idx - r * np;
            float* base = sm + r * ROWBUF;
            base[LOFF[L + 1] + i] = base[LOFF[L] + 2 * i] + base[LOFF[L] + 2 * i + 1];
        }
        __syncthreads();
    }

    // down-sweep: scan_L[2m+1] = scan_{L+1}[m]; scan_L[2m] = scan_{L+1}[m-1] + e_L[2m] (m>=1)
#pragma unroll
    for (int L = NLV - 2; L >= 0; --L) {
        const int n    = LLEN[L];
        const int half = n >> 1;                 // count of odd positions
        const int Ecnt = ((n + 1) >> 1) - 1;     // even m ranges 1..Ecnt
        for (int idx = tid; idx < 2 * half; idx += 256) {
            const int r = (idx < half) ? 0 : 1;
            const int m = idx - r * half;
            float* base = sm + r * ROWBUF;
            const int me = m + 1;
            if (me <= Ecnt)
                base[LOFF[L] + 2 * me] += base[LOFF[L + 1] + me - 1];
            base[LOFF[L] + 2 * m + 1] = base[LOFF[L + 1] + m];
        }
        __syncthreads();
    }

    // window difference + /3 (IEEE), write back in place
    for (int idx = tid; idx < 2 * Seq; idx += 256) {
        const int r = idx >> 11, s = idx & (Seq - 1);
        const float* C = sm + r * ROWBUF;        // LOFF[0] == 0
        const float a  = C[s + 2];
        const float bs = (s >= 1) ? C[s - 1] : 0.0f;
        g_xT[(grow0 + r) * Seq + s] = __fdiv_rn(a - bs, 3.0f);
    }
}

// ---------------- Kernel C: GEMM router_input[16384,1024] x proto^T -> logits ----------------
__global__ __launch_bounds__(256) void gemm_kernel(const float* __restrict__ proto)
{
    __shared__ __align__(16) float  Xs[32][68];
    __shared__ __align__(16) float2 Psd[32][Ee];

    const int tid = threadIdx.x;
    const int m0  = blockIdx.x * 64;          // global token base
    const int b   = m0 >> 11;
    const int sl0 = m0 & (Seq - 1);
    const int tx  = tid & 15;                 // 16 x 4 experts
    const int ty  = tid >> 4;                 // 16 x 4 tokens
    const int mqx = tid & 7;                  // X: float4 index along m
    const int kqx = tid >> 3;                 // X: k row 0..31
    const int pe  = tid >> 3;                 // proto rows pe, pe+32
    const int pk4 = (tid & 7) * 4;

    unsigned long long acc[2][2][4];
#pragma unroll
    for (int p = 0; p < 2; ++p)
#pragma unroll
        for (int i = 0; i < 2; ++i)
#pragma unroll
            for (int j = 0; j < 4; ++j) acc[p][i][j] = 0ull;

    const float* xb  = g_xT + ((size_t)b * Dd + kqx) * Seq + sl0;
    const float* pb0 = proto + (size_t)pe * Dd + pk4;
    const float* pb1 = pb0 + (size_t)32 * Dd;

    // prefetch chunk 0 (coalesced: consecutive tid -> consecutive t / d)
    float4 xa0 = *(const float4*)(xb + mqx * 4);
    float4 xa1 = *(const float4*)(xb + mqx * 4 + 32);
    float4 pa0 = *(const float4*)(pb0);
    float4 pa1 = *(const float4*)(pb1);

    for (int c = 0; c < 32; ++c) {
        __syncthreads();
        *(float4*)&Xs[kqx][mqx * 4]      = xa0;
        *(float4*)&Xs[kqx][mqx * 4 + 32] = xa1;

        Psd[pk4 + 0][pe] = make_float2(pa0.x, pa0.x);
        Psd[pk4 + 1][pe] = make_float2(pa0.y, pa0.y);
        Psd[pk4 + 2][pe] = make_float2(pa0.z, pa0.z);
        Psd[pk4 + 3][pe] = make_float2(pa0.w, pa0.w);
        Psd[pk4 + 0][pe + 32] = make_float2(pa1.x, pa1.x);
        Psd[pk4 + 1][pe + 32] = make_float2(pa1.y, pa1.y);
        Psd[pk4 + 2][pe + 32] = make_float2(pa1.z, pa1.z);
        Psd[pk4 + 3][pe + 32] = make_float2(pa1.w, pa1.w);
        __syncthreads();

        if (c + 1 < 32) {   // prefetch next chunk
            const float* xn = xb + (size_t)(c + 1) * 32 * Seq;
            xa0 = *(const float4*)(xn + mqx * 4);
            xa1 = *(const float4*)(xn + mqx * 4 + 32);
            pa0 = *(const float4*)(pb0 + (c + 1) * 32);
            pa1 = *(const float4*)(pb1 + (c + 1) * 32);
        }

        const int par = c & 1;
#pragma unroll
        for (int kk = 0; kk < 32; ++kk) {
            const ulonglong2 a  = *(const ulonglong2*)&Xs[kk][ty * 4];
            const ulonglong2 bA = *(const ulonglong2*)&Psd[kk][tx * 4];
            const ulonglong2 bB = *(const ulonglong2*)&Psd[kk][tx * 4 + 2];
            FMA2(acc[par][0][0], a.x, bA.x);  FMA2(acc[par][1][0], a.y, bA.x);
            FMA2(acc[par][0][1], a.x, bA.y);  FMA2(acc[par][1][1], a.y, bA.y);
            FMA2(acc[par][0][2], a.x, bB.x);  FMA2(acc[par][1][2], a.y, bB.x);
            FMA2(acc[par][0][3], a.x, bB.y);  FMA2(acc[par][1][3], a.y, bB.y);
        }
    }

    // combine parity halves, write logits
    const int r0 = m0 + ty * 4;
#pragma unroll
    for (int im = 0; im < 2; ++im) {
        union { unsigned long long u; float2 f; } c0, c1;
        float4 vlo, vhi;
        c0.u = acc[0][im][0]; c1.u = acc[1][im][0];
        vlo.x = c0.f.x + c1.f.x; vhi.x = c0.f.y + c1.f.y;
        c0.u = acc[0][im][1]; c1.u = acc[1][im][1];
        vlo.y = c0.f.x + c1.f.x; vhi.y = c0.f.y + c1.f.y;
        c0.u = acc[0][im][2]; c1.u = acc[1][im][2];
        vlo.z = c0.f.x + c1.f.x; vhi.z = c0.f.y + c1.f.y;
        c0.u = acc[0][im][3]; c1.u = acc[1][im][3];
        vlo.w = c0.f.x + c1.f.x; vhi.w = c0.f.y + c1.f.y;
        const int r = r0 + im * 2;
        *(float4*)&g_z[(size_t)r       * Ee + tx * 4] = vlo;
        *(float4*)&g_z[(size_t)(r + 1) * Ee + tx * 4] = vhi;
    }
}

// ---------------- Kernel D: softmax + top-2 (selection on logits) ----------------
__global__ __launch_bounds__(256) void epilogue_kernel(float* __restrict__ out, int half)
{
    const int warp = (blockIdx.x * blockDim.x + threadIdx.x) >> 5;
    const int lane = threadIdx.x & 31;
    if (warp >= Mtot) return;
    const int t = warp;
    const int e0 = lane, e1 = lane + 32;

    const float l0 = g_z[(size_t)t * Ee + e0];
    const float l1 = g_z[(size_t)t * Ee + e1];

    // top-1 on logits (ties -> lower index, matching jax.lax.top_k)
    float bv = l0; int bi = e0;
    if (l1 > bv) { bv = l1; bi = e1; }
#pragma unroll
    for (int o = 16; o; o >>= 1) {
        const float ov = __shfl_xor_sync(FULLMASK, bv, o);
        const int   oi = __shfl_xor_sync(FULLMASK, bi, o);
        if (ov > bv || (ov == bv && oi < bi)) { bv = ov; bi = oi; }
    }
    const int i1 = bi; const float v1 = bv;     // v1 is also the row max

    // top-2
    float c0 = (e0 == i1) ? -FLT_MAX : l0;
    float c1 = (e1 == i1) ? -FLT_MAX : l1;
    bv = c0; bi = e0;
    if (c1 > bv) { bv = c1; bi = e1; }
#pragma unroll
    for (int o = 16; o; o >>= 1) {
        const float ov = __shfl_xor_sync(FULLMASK, bv, o);
        const int   oi = __shfl_xor_sync(FULLMASK, bi, o);
        if (ov > bv || (ov == bv && oi < bi)) { bv = ov; bi = oi; }
    }
    const int i2 = bi; const float v2 = bv;

    // softmax weights (fp32, max-shifted), then renormalize the top-2 pair
    const float mx = v1;
    float sm = expf(l0 - mx) + expf(l1 - mx);
#pragma unroll
    for (int o = 16; o; o >>= 1) sm += __shfl_xor_sync(FULLMASK, sm, o);

    if (lane == 0) {
        const float p1 = __fdiv_rn(expf(v1 - mx), sm);
        const float p2 = __fdiv_rn(expf(v2 - mx), sm);
        const float den = p1 + p2;
        out[(size_t)t * 2 + 0] = (float)i1;
        out[(size_t)t * 2 + 1] = (float)i2;
        out[(size_t)half + (size_t)t * 2 + 0] = __fdiv_rn(p1, den);
        out[(size_t)half + (size_t)t * 2 + 1] = __fdiv_rn(p2, den);
    }
}

extern "C" void kernel_launch(void* const* d_in, const int* in_sizes, int n_in,
                              void* d_out, int out_size)
{
    const float* x = nullptr;
    const float* p = nullptr;
    for (int i = 0; i < n_in; ++i) {
        if (in_sizes[i] == Mtot * Dd)      x = (const float*)d_in[i];
        else if (in_sizes[i] == Ee * Dd)   p = (const float*)d_in[i];
    }

    // A: norms
    norm_kernel<<<Mtot / 8, 256>>>(x);
    // B1: transpose + normalize
    transpose_norm_kernel<<<dim3(Seq / 32, Dd / 32, Bb), dim3(32, 8)>>>(x);
    // B2: associative-scan cumsum emulation + window mean (in place)
    scan_kernel<<<Bb * Dd / 2, 256>>>();
    // C: GEMM -> logits
    gemm_kernel<<<Mtot / 64, 256>>>(p);
    // D: softmax/top-2
    float* out = (float*)d_out;
    const int half = out_size / 2;
    epilogue_kernel<<<(Mtot * 32 + 255) / 256, 256>>>(out, half);
}

// round 11
// speedup vs baseline: 1.0992x; 1.0992x over previous
#include <cuda_runtime.h>
#include <math.h>
#include <float.h>

#define FULLMASK 0xFFFFFFFFu

constexpr int Bb   = 8;
constexpr int Seq  = 2048;
constexpr int Dd   = 1024;
constexpr int Ee   = 64;
constexpr int Mtot = Bb * Seq;          // 16384 tokens

constexpr int ROWBUF = 4100;            // 4098 + pad (scan scratch per row)

// scratch (no cudaMalloc allowed)
__device__ float g_nrm[Mtot];
__device__ float g_xT[(size_t)Bb * Dd * Seq];   // [b*D+d][t]; later overwritten with router_input
__device__ float g_zp[2][(size_t)Mtot * Ee];    // split-K partial logits (even/odd chunk classes)

// packed fp32x2 FMA (sm_100+)
#define FMA2(c, a, b) asm("fma.rn.f32x2 %0, %1, %2, %0;" : "+l"(c) : "l"(a), "l"(b))

// ---------------- Kernel A: per-token norms ----------------
__global__ __launch_bounds__(256) void norm_kernel(const float* __restrict__ x)
{
    const int warp = (blockIdx.x * blockDim.x + threadIdx.x) >> 5;
    const int lane = threadIdx.x & 31;
    if (warp >= Mtot) return;
    const float4* px = (const float4*)(x + (size_t)warp * Dd);
    float s0 = 0.f, s1 = 0.f, s2 = 0.f, s3 = 0.f;
#pragma unroll
    for (int j = 0; j < 8; ++j) {
        const float4 v = px[lane + 32 * j];
        s0 += v.x * v.x;  s1 += v.y * v.y;
        s2 += v.z * v.z;  s3 += v.w * v.w;
    }
    float s = (s0 + s1) + (s2 + s3);
#pragma unroll
    for (int o = 16; o; o >>= 1) s += __shfl_xor_sync(FULLMASK, s, o);
    if (lane == 0) g_nrm[warp] = fmaxf(__fsqrt_rn(s), 1e-8f);
}

// ---------------- Kernel B1: transpose + normalize (IEEE division) ----------------
__global__ void transpose_norm_kernel(const float* __restrict__ x)
{
    __shared__ float tile[32][33];
    const int b  = blockIdx.z;
    const int t0 = blockIdx.x * 32;
    const int d0 = blockIdx.y * 32;
    const int tx = threadIdx.x, ty = threadIdx.y;

#pragma unroll
    for (int i = 0; i < 4; ++i) {
        const int t = t0 + ty + i * 8;
        tile[ty + i * 8][tx] = x[((size_t)b * Seq + t) * Dd + d0 + tx];
    }
    __syncthreads();
    const float rn = g_nrm[b * Seq + t0 + tx];
#pragma unroll
    for (int i = 0; i < 4; ++i) {
        const int d = d0 + ty + i * 8;
        g_xT[((size_t)b * Dd + d) * Seq + t0 + tx] = __fdiv_rn(tile[tx][ty + i * 8], rn);
    }
}

// ---------------- Kernel B2: emulate jax associative_scan cumsum + window ----------------
// Per (b,d) row: padded = [x0, x0, x0..x_{S-1}] (len 2050), C = inclusive Blelloch scan,
// router_input[s] = (C[s+2] - (s>=1 ? C[s-1] : 0)) / 3, written in place over g_xT.
__global__ __launch_bounds__(256) void scan_kernel()
{
    constexpr int NLV = 12;
    constexpr int LLEN[NLV] = {2050,1025,512,256,128,64,32,16,8,4,2,1};
    constexpr int LOFF[NLV] = {0,2050,3075,3587,3843,3971,4035,4067,4083,4091,4095,4097};

    __shared__ float sm[2 * ROWBUF];
    const int tid = threadIdx.x;
    const size_t grow0 = (size_t)blockIdx.x * 2;

    for (int idx = tid; idx < 2 * Seq; idx += 256) {
        const int r = idx >> 11, t = idx & (Seq - 1);
        sm[r * ROWBUF + 2 + t] = g_xT[(grow0 + r) * Seq + t];
    }
    __syncthreads();
    if (tid < 2) {
        const float v = sm[tid * ROWBUF + 2];
        sm[tid * ROWBUF + 0] = v;
        sm[tid * ROWBUF + 1] = v;
    }
    __syncthreads();

#pragma unroll
    for (int L = 0; L < NLV - 1; ++L) {
        const int np = LLEN[L + 1];
        for (int idx = tid; idx < 2 * np; idx += 256) {
            const int r = (idx < np) ? 0 : 1;
            const int i = idx - r * np;
            float* base = sm + r * ROWBUF;
            base[LOFF[L + 1] + i] = base[LOFF[L] + 2 * i] + base[LOFF[L] + 2 * i + 1];
        }
        __syncthreads();
    }

#pragma unroll
    for (int L = NLV - 2; L >= 0; --L) {
        const int n    = LLEN[L];
        const int half = n >> 1;
        const int Ecnt = ((n + 1) >> 1) - 1;
        for (int idx = tid; idx < 2 * half; idx += 256) {
            const int r = (idx < half) ? 0 : 1;
            const int m = idx - r * half;
            float* base = sm + r * ROWBUF;
            const int me = m + 1;
            if (me <= Ecnt)
                base[LOFF[L] + 2 * me] += base[LOFF[L + 1] + me - 1];
            base[LOFF[L] + 2 * m + 1] = base[LOFF[L + 1] + m];
        }
        __syncthreads();
    }

    for (int idx = tid; idx < 2 * Seq; idx += 256) {
        const int r = idx >> 11, s = idx & (Seq - 1);
        const float* C = sm + r * ROWBUF;
        const float a  = C[s + 2];
        const float bs = (s >= 1) ? C[s - 1] : 0.0f;
        g_xT[(grow0 + r) * Seq + s] = __fdiv_rn(a - bs, 3.0f);
    }
}

// ---------------- Kernel C: split-K-parity GEMM, 8M x 8E per thread ----------------
// blockIdx.x: 128-token M block; blockIdx.y: chunk-parity class (0=even,1=odd).
// Each block accumulates its 16 chunks (c = 2*ci + par) in ascending order into a
// single acc chain — combined with the epilogue's (even + odd) add this is
// arithmetically IDENTICAL to the round-7 kernel's acc[c&1] parity split.
__global__ __launch_bounds__(128) void gemm_kernel(const float* __restrict__ proto)
{
    __shared__ __align__(16) float  Xs[32][128];    // [k][m]  (row stride 512B, 16B-aligned)
    __shared__ __align__(16) float2 Psd[32][66];    // [k][e] dup pairs; stride 528B = 33*16 (16B-aligned!)

    const int tid = threadIdx.x;
    const int m0  = blockIdx.x * 128;
    const int par = blockIdx.y;
    const int b   = m0 >> 11;
    const int sl0 = m0 & (Seq - 1);
    const int tx  = tid & 7;             // experts tx*8 .. tx*8+7
    const int ty  = tid >> 3;            // tokens  ty*8 .. ty*8+7 (m-pairs packed in f32x2)

    unsigned long long acc[4][8];        // [m-pair][e]
#pragma unroll
    for (int i = 0; i < 4; ++i)
#pragma unroll
        for (int j = 0; j < 8; ++j) acc[i][j] = 0ull;

    for (int ci = 0; ci < 16; ++ci) {
        const int ck = (2 * ci + par) * 32;   // chunk k base
        __syncthreads();

        // stage Xs[32][128] from g_xT (m-contiguous, coalesced)
        for (int i = tid; i < 32 * 32; i += 128) {       // 8 iters, float4 each
            const int k = i >> 5, m4 = (i & 31) * 4;
            *(float4*)&Xs[k][m4] =
                *(const float4*)&g_xT[((size_t)(b * Dd + ck + k)) * Seq + sl0 + m4];
        }
        // stage Psd: proto[e][ck+k4..+3] -> duplicated float2 per k
        for (int i = tid; i < 512; i += 128) {           // 4 iters
            const int e = i >> 3, k4 = (i & 7) * 4;
            const float4 pv = *(const float4*)&proto[(size_t)e * Dd + ck + k4];
            Psd[k4 + 0][e] = make_float2(pv.x, pv.x);
            Psd[k4 + 1][e] = make_float2(pv.y, pv.y);
            Psd[k4 + 2][e] = make_float2(pv.z, pv.z);
            Psd[k4 + 3][e] = make_float2(pv.w, pv.w);
        }
        __syncthreads();

#pragma unroll
        for (int kk = 0; kk < 32; ++kk) {
            const ulonglong2 a0 = *(const ulonglong2*)&Xs[kk][ty * 8];
            const ulonglong2 a1 = *(const ulonglong2*)&Xs[kk][ty * 8 + 4];
            const ulonglong2 b0 = *(const ulonglong2*)&Psd[kk][tx * 8];
            const ulonglong2 b1 = *(const ulonglong2*)&Psd[kk][tx * 8 + 2];
            const ulonglong2 b2 = *(const ulonglong2*)&Psd[kk][tx * 8 + 4];
            const ulonglong2 b3 = *(const ulonglong2*)&Psd[kk][tx * 8 + 6];
            const unsigned long long ap[4] = {a0.x, a0.y, a1.x, a1.y};
            const unsigned long long bp[8] = {b0.x, b0.y, b1.x, b1.y, b2.x, b2.y, b3.x, b3.y};
#pragma unroll
            for (int mi = 0; mi < 4; ++mi)
#pragma unroll
                for (int e = 0; e < 8; ++e)
                    FMA2(acc[mi][e], ap[mi], bp[e]);
        }
    }

    // write partial logits (e-contiguous, coalesced)
    float* zp = g_zp[par];
    const int mbase = m0 + ty * 8;
#pragma unroll
    for (int mi = 0; mi < 4; ++mi) {
        union { unsigned long long u; float2 f; } cv;
        float lo[8], hi[8];
#pragma unroll
        for (int e = 0; e < 8; ++e) {
            cv.u = acc[mi][e];
            lo[e] = cv.f.x;  hi[e] = cv.f.y;
        }
        const size_t r0 = ((size_t)(mbase + mi * 2)) * Ee + tx * 8;
        *(float4*)&zp[r0]          = make_float4(lo[0], lo[1], lo[2], lo[3]);
        *(float4*)&zp[r0 + 4]      = make_float4(lo[4], lo[5], lo[6], lo[7]);
        *(float4*)&zp[r0 + Ee]     = make_float4(hi[0], hi[1], hi[2], hi[3]);
        *(float4*)&zp[r0 + Ee + 4] = make_float4(hi[4], hi[5], hi[6], hi[7]);
    }
}

// ---------------- Kernel D: combine partials + softmax + top-2 ----------------
__global__ __launch_bounds__(256) void epilogue_kernel(float* __restrict__ out, int half)
{
    const int warp = (blockIdx.x * blockDim.x + threadIdx.x) >> 5;
    const int lane = threadIdx.x & 31;
    if (warp >= Mtot) return;
    const int t = warp;
    const int e0 = lane, e1 = lane + 32;

    // even + odd (same order as round-7's parity combine)
    const float l0 = g_zp[0][(size_t)t * Ee + e0] + g_zp[1][(size_t)t * Ee + e0];
    const float l1 = g_zp[0][(size_t)t * Ee + e1] + g_zp[1][(size_t)t * Ee + e1];

    // top-1 on logits (ties -> lower index, matching jax.lax.top_k)
    float bv = l0; int bi = e0;
    if (l1 > bv) { bv = l1; bi = e1; }
#pragma unroll
    for (int o = 16; o; o >>= 1) {
        const float ov = __shfl_xor_sync(FULLMASK, bv, o);
        const int   oi = __shfl_xor_sync(FULLMASK, bi, o);
        if (ov > bv || (ov == bv && oi < bi)) { bv = ov; bi = oi; }
    }
    const int i1 = bi; const float v1 = bv;     // also the row max

    // top-2
    float c0 = (e0 == i1) ? -FLT_MAX : l0;
    float c1 = (e1 == i1) ? -FLT_MAX : l1;
    bv = c0; bi = e0;
    if (c1 > bv) { bv = c1; bi = e1; }
#pragma unroll
    for (int o = 16; o; o >>= 1) {
        const float ov = __shfl_xor_sync(FULLMASK, bv, o);
        const int   oi = __shfl_xor_sync(FULLMASK, bi, o);
        if (ov > bv || (ov == bv && oi < bi)) { bv = ov; bi = oi; }
    }
    const int i2 = bi; const float v2 = bv;

    // softmax weights (fp32, max-shifted), renormalize the top-2 pair
    const float mx = v1;
    float sm = expf(l0 - mx) + expf(l1 - mx);
#pragma unroll
    for (int o = 16; o; o >>= 1) sm += __shfl_xor_sync(FULLMASK, sm, o);

    if (lane == 0) {
        const float p1 = __fdiv_rn(expf(v1 - mx), sm);
        const float p2 = __fdiv_rn(expf(v2 - mx), sm);
        const float den = p1 + p2;
        out[(size_t)t * 2 + 0] = (float)i1;
        out[(size_t)t * 2 + 1] = (float)i2;
        out[(size_t)half + (size_t)t * 2 + 0] = __fdiv_rn(p1, den);
        out[(size_t)half + (size_t)t * 2 + 1] = __fdiv_rn(p2, den);
    }
}

extern "C" void kernel_launch(void* const* d_in, const int* in_sizes, int n_in,
                              void* d_out, int out_size)
{
    const float* x = nullptr;
    const float* p = nullptr;
    for (int i = 0; i < n_in; ++i) {
        if (in_sizes[i] == Mtot * Dd)      x = (const float*)d_in[i];
        else if (in_sizes[i] == Ee * Dd)   p = (const float*)d_in[i];
    }

    norm_kernel<<<Mtot / 8, 256>>>(x);
    transpose_norm_kernel<<<dim3(Seq / 32, Dd / 32, Bb), dim3(32, 8)>>>(x);
    scan_kernel<<<Bb * Dd / 2, 256>>>();
    gemm_kernel<<<dim3(Mtot / 128, 2), 128>>>(p);

    float* out = (float*)d_out;
    const int half = out_size / 2;
    epilogue_kernel<<<(Mtot * 32 + 255) / 256, 256>>>(out, half);
}

// round 13
// speedup vs baseline: 1.1254x; 1.0238x over previous
#include <cuda_runtime.h>
#include <math.h>
#include <float.h>

#define FULLMASK 0xFFFFFFFFu

constexpr int Bb   = 8;
constexpr int Seq  = 2048;
constexpr int Dd   = 1024;
constexpr int Ee   = 64;
constexpr int Mtot = Bb * Seq;          // 16384 tokens

constexpr int ROWBUF = 4100;            // 4098 + pad (scan scratch per row)

// scratch (no cudaMalloc allowed)
__device__ float g_nrm[Mtot];
__device__ float g_xT[(size_t)Bb * Dd * Seq];   // [b*D+d][t]; later overwritten with router_input
__device__ float g_zp[2][(size_t)Mtot * Ee];    // split-K partial logits (even/odd chunk classes)

// packed fp32x2 FMA (sm_100+)
#define FMA2(c, a, b) asm("fma.rn.f32x2 %0, %1, %2, %0;" : "+l"(c) : "l"(a), "l"(b))

// ---------------- Kernel A: per-token norms ----------------
__global__ __launch_bounds__(256) void norm_kernel(const float* __restrict__ x)
{
    const int warp = (blockIdx.x * blockDim.x + threadIdx.x) >> 5;
    const int lane = threadIdx.x & 31;
    if (warp >= Mtot) return;
    const float4* px = (const float4*)(x + (size_t)warp * Dd);
    float s0 = 0.f, s1 = 0.f, s2 = 0.f, s3 = 0.f;
#pragma unroll
    for (int j = 0; j < 8; ++j) {
        const float4 v = px[lane + 32 * j];
        s0 += v.x * v.x;  s1 += v.y * v.y;
        s2 += v.z * v.z;  s3 += v.w * v.w;
    }
    float s = (s0 + s1) + (s2 + s3);
#pragma unroll
    for (int o = 16; o; o >>= 1) s += __shfl_xor_sync(FULLMASK, s, o);
    if (lane == 0) g_nrm[warp] = fmaxf(__fsqrt_rn(s), 1e-8f);
}

// ---------------- Kernel B1: transpose + normalize (IEEE division) ----------------
__global__ void transpose_norm_kernel(const float* __restrict__ x)
{
    __shared__ float tile[32][33];
    const int b  = blockIdx.z;
    const int t0 = blockIdx.x * 32;
    const int d0 = blockIdx.y * 32;
    const int tx = threadIdx.x, ty = threadIdx.y;

#pragma unroll
    for (int i = 0; i < 4; ++i) {
        const int t = t0 + ty + i * 8;
        tile[ty + i * 8][tx] = x[((size_t)b * Seq + t) * Dd + d0 + tx];
    }
    __syncthreads();
    const float rn = g_nrm[b * Seq + t0 + tx];
#pragma unroll
    for (int i = 0; i < 4; ++i) {
        const int d = d0 + ty + i * 8;
        g_xT[((size_t)b * Dd + d) * Seq + t0 + tx] = __fdiv_rn(tile[tx][ty + i * 8], rn);
    }
}

// ---------------- Kernel B2: emulate jax associative_scan cumsum + window ----------------
// Per (b,d) row: padded = [x0, x0, x0..x_{S-1}] (len 2050), C = inclusive Blelloch scan,
// router_input[s] = (C[s+2] - (s>=1 ? C[s-1] : 0)) / 3, written in place over g_xT.
__global__ __launch_bounds__(256) void scan_kernel()
{
    constexpr int NLV = 12;
    constexpr int LLEN[NLV] = {2050,1025,512,256,128,64,32,16,8,4,2,1};
    constexpr int LOFF[NLV] = {0,2050,3075,3587,3843,3971,4035,4067,4083,4091,4095,4097};

    __shared__ float sm[2 * ROWBUF];
    const int tid = threadIdx.x;
    const size_t grow0 = (size_t)blockIdx.x * 2;

    for (int idx = tid; idx < 2 * Seq; idx += 256) {
        const int r = idx >> 11, t = idx & (Seq - 1);
        sm[r * ROWBUF + 2 + t] = g_xT[(grow0 + r) * Seq + t];
    }
    __syncthreads();
    if (tid < 2) {
        const float v = sm[tid * ROWBUF + 2];
        sm[tid * ROWBUF + 0] = v;
        sm[tid * ROWBUF + 1] = v;
    }
    __syncthreads();

#pragma unroll
    for (int L = 0; L < NLV - 1; ++L) {
        const int np = LLEN[L + 1];
        for (int idx = tid; idx < 2 * np; idx += 256) {
            const int r = (idx < np) ? 0 : 1;
            const int i = idx - r * np;
            float* base = sm + r * ROWBUF;
            base[LOFF[L + 1] + i] = base[LOFF[L] + 2 * i] + base[LOFF[L] + 2 * i + 1];
        }
        __syncthreads();
    }

#pragma unroll
    for (int L = NLV - 2; L >= 0; --L) {
        const int n    = LLEN[L];
        const int half = n >> 1;
        const int Ecnt = ((n + 1) >> 1) - 1;
        for (int idx = tid; idx < 2 * half; idx += 256) {
            const int r = (idx < half) ? 0 : 1;
            const int m = idx - r * half;
            float* base = sm + r * ROWBUF;
            const int me = m + 1;
            if (me <= Ecnt)
                base[LOFF[L] + 2 * me] += base[LOFF[L + 1] + me - 1];
            base[LOFF[L] + 2 * m + 1] = base[LOFF[L + 1] + m];
        }
        __syncthreads();
    }

    for (int idx = tid; idx < 2 * Seq; idx += 256) {
        const int r = idx >> 11, s = idx & (Seq - 1);
        const float* C = sm + r * ROWBUF;
        const float a  = C[s + 2];
        const float bs = (s >= 1) ? C[s - 1] : 0.0f;
        g_xT[(grow0 + r) * Seq + s] = __fdiv_rn(a - bs, 3.0f);
    }
}

// ---------------- Kernel C: split-K-parity GEMM, 8M x 8E per thread ----------------
// blockIdx.x: 128-token M block; blockIdx.y: chunk-parity class (0=even,1=odd).
// Accumulation chain per output element identical to round-7's parity accumulators
// (ascending chunks within class, kk ascending) -> bit-identical results.
// This round: next-chunk X tile prefetched into registers DURING the FMA loop
// (restores the R7 software pipeline dropped in R8; the LDG latency was fully
// exposed inside the sync window at 6.9 warps/SM).
__global__ __launch_bounds__(128) void gemm_kernel(const float* __restrict__ proto)
{
    __shared__ __align__(16) float  Xs[32][128];    // [k][m]  (row stride 512B, 16B-aligned)
    __shared__ __align__(16) float2 Psd[32][66];    // [k][e] dup pairs; stride 528B = 33*16

    const int tid = threadIdx.x;
    const int m0  = blockIdx.x * 128;
    const int par = blockIdx.y;
    const int b   = m0 >> 11;
    const int sl0 = m0 & (Seq - 1);
    const int tx  = tid & 7;             // experts tx*8 .. tx*8+7
    const int ty  = tid >> 3;            // tokens  ty*8 .. ty*8+7 (m-pairs packed in f32x2)
    const int kr  = tid >> 5;            // X staging: base k row (0..3)
    const int m4  = (tid & 31) * 4;      // X staging: m offset

    unsigned long long acc[4][8];        // [m-pair][e]
#pragma unroll
    for (int i = 0; i < 4; ++i)
#pragma unroll
        for (int j = 0; j < 8; ++j) acc[i][j] = 0ull;

    // X stream base for this thread: rows kr+4j of each chunk, column m4
    const float* xbase = g_xT + ((size_t)(b * Dd + kr)) * Seq + sl0 + m4;

    // prefetch chunk ci=0 (k base = par*32)
    float4 xa[8];
#pragma unroll
    for (int j = 0; j < 8; ++j)
        xa[j] = *(const float4*)(xbase + ((size_t)(par * 32 + 4 * j)) * Seq);

    for (int ci = 0; ci < 16; ++ci) {
        const int ck = (2 * ci + par) * 32;   // current chunk k base
        __syncthreads();

        // stage prefetched X into smem
#pragma unroll
        for (int j = 0; j < 8; ++j)
            *(float4*)&Xs[kr + 4 * j][m4] = xa[j];

        // stage Psd: proto[e][ck+k4..+3] -> duplicated float2 per k  (L1/L2-hot)
        for (int i = tid; i < 512; i += 128) {           // 4 iters
            const int e = i >> 3, k4 = (i & 7) * 4;
            const float4 pv = *(const float4*)&proto[(size_t)e * Dd + ck + k4];
            Psd[k4 + 0][e] = make_float2(pv.x, pv.x);
            Psd[k4 + 1][e] = make_float2(pv.y, pv.y);
            Psd[k4 + 2][e] = make_float2(pv.z, pv.z);
            Psd[k4 + 3][e] = make_float2(pv.w, pv.w);
        }
        __syncthreads();

        // prefetch next chunk's X into registers (overlaps with FMA loop below)
        if (ci + 1 < 16) {
            const int ckn = (2 * (ci + 1) + par) * 32;
#pragma unroll
            for (int j = 0; j < 8; ++j)
                xa[j] = *(const float4*)(xbase + ((size_t)(ckn + 4 * j)) * Seq);
        }

#pragma unroll
        for (int kk = 0; kk < 32; ++kk) {
            const ulonglong2 a0 = *(const ulonglong2*)&Xs[kk][ty * 8];
            const ulonglong2 a1 = *(const ulonglong2*)&Xs[kk][ty * 8 + 4];
            const ulonglong2 b0 = *(const ulonglong2*)&Psd[kk][tx * 8];
            const ulonglong2 b1 = *(const ulonglong2*)&Psd[kk][tx * 8 + 2];
            const ulonglong2 b2 = *(const ulonglong2*)&Psd[kk][tx * 8 + 4];
            const ulonglong2 b3 = *(const ulonglong2*)&Psd[kk][tx * 8 + 6];
            const unsigned long long ap[4] = {a0.x, a0.y, a1.x, a1.y};
            const unsigned long long bp[8] = {b0.x, b0.y, b1.x, b1.y, b2.x, b2.y, b3.x, b3.y};
#pragma unroll
            for (int mi = 0; mi < 4; ++mi)
#pragma unroll
                for (int e = 0; e < 8; ++e)
                    FMA2(acc[mi][e], ap[mi], bp[e]);
        }
    }

    // write partial logits (e-contiguous, coalesced)
    float* zp = g_zp[par];
    const int mbase = m0 + ty * 8;
#pragma unroll
    for (int mi = 0; mi < 4; ++mi) {
        union { unsigned long long u; float2 f; } cv;
        float lo[8], hi[8];
#pragma unroll
        for (int e = 0; e < 8; ++e) {
            cv.u = acc[mi][e];
            lo[e] = cv.f.x;  hi[e] = cv.f.y;
        }
        const size_t r0 = ((size_t)(mbase + mi * 2)) * Ee + tx * 8;
        *(float4*)&zp[r0]          = make_float4(lo[0], lo[1], lo[2], lo[3]);
        *(float4*)&zp[r0 + 4]      = make_float4(lo[4], lo[5], lo[6], lo[7]);
        *(float4*)&zp[r0 + Ee]     = make_float4(hi[0], hi[1], hi[2], hi[3]);
        *(float4*)&zp[r0 + Ee + 4] = make_float4(hi[4], hi[5], hi[6], hi[7]);
    }
}

// ---------------- Kernel D: combine partials + softmax + top-2 ----------------
__global__ __launch_bounds__(256) void epilogue_kernel(float* __restrict__ out, int half)
{
    const int warp = (blockIdx.x * blockDim.x + threadIdx.x) >> 5;
    const int lane = threadIdx.x & 31;
    if (warp >= Mtot) return;
    const int t = warp;
    const int e0 = lane, e1 = lane + 32;

    // even + odd (same order as round-7's parity combine)
    const float l0 = g_zp[0][(size_t)t * Ee + e0] + g_zp[1][(size_t)t * Ee + e0];
    const float l1 = g_zp[0][(size_t)t * Ee + e1] + g_zp[1][(size_t)t * Ee + e1];

    // top-1 on logits (ties -> lower index, matching jax.lax.top_k)
    float bv = l0; int bi = e0;
    if (l1 > bv) { bv = l1; bi = e1; }
#pragma unroll
    for (int o = 16; o; o >>= 1) {
        const float ov = __shfl_xor_sync(FULLMASK, bv, o);
        const int   oi = __shfl_xor_sync(FULLMASK, bi, o);
        if (ov > bv || (ov == bv && oi < bi)) { bv = ov; bi = oi; }
    }
    const int i1 = bi; const float v1 = bv;     // also the row max

    // top-2
    float c0 = (e0 == i1) ? -FLT_MAX : l0;
    float c1 = (e1 == i1) ? -FLT_MAX : l1;
    bv = c0; bi = e0;
    if (c1 > bv) { bv = c1; bi = e1; }
#pragma unroll
    for (int o = 16; o; o >>= 1) {
        const float ov = __shfl_xor_sync(FULLMASK, bv, o);
        const int   oi = __shfl_xor_sync(FULLMASK, bi, o);
        if (ov > bv || (ov == bv && oi < bi)) { bv = ov; bi = oi; }
    }
    const int i2 = bi; const float v2 = bv;

    // softmax weights (fp32, max-shifted), renormalize the top-2 pair
    const float mx = v1;
    float sm = expf(l0 - mx) + expf(l1 - mx);
#pragma unroll
    for (int o = 16; o; o >>= 1) sm += __shfl_xor_sync(FULLMASK, sm, o);

    if (lane == 0) {
        const float p1 = __fdiv_rn(expf(v1 - mx), sm);
        const float p2 = __fdiv_rn(expf(v2 - mx), sm);
        const float den = p1 + p2;
        out[(size_t)t * 2 + 0] = (float)i1;
        out[(size_t)t * 2 + 1] = (float)i2;
        out[(size_t)half + (size_t)t * 2 + 0] = __fdiv_rn(p1, den);
        out[(size_t)half + (size_t)t * 2 + 1] = __fdiv_rn(p2, den);
    }
}

extern "C" void kernel_launch(void* const* d_in, const int* in_sizes, int n_in,
                              void* d_out, int out_size)
{
    const float* x = nullptr;
    const float* p = nullptr;
    for (int i = 0; i < n_in; ++i) {
        if (in_sizes[i] == Mtot * Dd)      x = (const float*)d_in[i];
        else if (in_sizes[i] == Ee * Dd)   p = (const float*)d_in[i];
    }

    norm_kernel<<<Mtot / 8, 256>>>(x);
    transpose_norm_kernel<<<dim3(Seq / 32, Dd / 32, Bb), dim3(32, 8)>>>(x);
    scan_kernel<<<Bb * Dd / 2, 256>>>();
    gemm_kernel<<<dim3(Mtot / 128, 2), 128>>>(p);

    float* out = (float*)d_out;
    const int half = out_size / 2;
    epilogue_kernel<<<(Mtot * 32 + 255) / 256, 256>>>(out, half);
}

// round 14
// speedup vs baseline: 1.6350x; 1.4528x over previous
#include <cuda_runtime.h>
#include <math.h>
#include <float.h>

#define FULLMASK 0xFFFFFFFFu

constexpr int Bb   = 8;
constexpr int Seq  = 2048;
constexpr int Dd   = 1024;
constexpr int Ee   = 64;
constexpr int Mtot = Bb * Seq;          // 16384 tokens

constexpr int ROWBUF = 4100;            // 4098 + pad (scan scratch per row)

// scratch (no cudaMalloc allowed)
__device__ float g_nrm[Mtot];
__device__ float g_xT[(size_t)Bb * Dd * Seq];   // [b*D+d][t]; later overwritten with router_input
__device__ float g_zp[2][(size_t)Mtot * Ee];    // split-K partial logits (even/odd chunk classes)

// packed fp32x2 FMA (sm_100+)
#define FMA2(c, a, b) asm("fma.rn.f32x2 %0, %1, %2, %0;" : "+l"(c) : "l"(a), "l"(b))
// duplicate one fp32 into both lanes of a packed f32x2 (ALU, cheap)
#define DUP2(d, s)    asm("mov.b64 %0, {%1, %1};" : "=l"(d) : "f"(s))

// ---------------- Kernel A: per-token norms ----------------
__global__ __launch_bounds__(256) void norm_kernel(const float* __restrict__ x)
{
    const int warp = (blockIdx.x * blockDim.x + threadIdx.x) >> 5;
    const int lane = threadIdx.x & 31;
    if (warp >= Mtot) return;
    const float4* px = (const float4*)(x + (size_t)warp * Dd);
    float s0 = 0.f, s1 = 0.f, s2 = 0.f, s3 = 0.f;
#pragma unroll
    for (int j = 0; j < 8; ++j) {
        const float4 v = px[lane + 32 * j];
        s0 += v.x * v.x;  s1 += v.y * v.y;
        s2 += v.z * v.z;  s3 += v.w * v.w;
    }
    float s = (s0 + s1) + (s2 + s3);
#pragma unroll
    for (int o = 16; o; o >>= 1) s += __shfl_xor_sync(FULLMASK, s, o);
    if (lane == 0) g_nrm[warp] = fmaxf(__fsqrt_rn(s), 1e-8f);
}

// ---------------- Kernel B1: transpose + normalize (IEEE division) ----------------
__global__ void transpose_norm_kernel(const float* __restrict__ x)
{
    __shared__ float tile[32][33];
    const int b  = blockIdx.z;
    const int t0 = blockIdx.x * 32;
    const int d0 = blockIdx.y * 32;
    const int tx = threadIdx.x, ty = threadIdx.y;

#pragma unroll
    for (int i = 0; i < 4; ++i) {
        const int t = t0 + ty + i * 8;
        tile[ty + i * 8][tx] = x[((size_t)b * Seq + t) * Dd + d0 + tx];
    }
    __syncthreads();
    const float rn = g_nrm[b * Seq + t0 + tx];
#pragma unroll
    for (int i = 0; i < 4; ++i) {
        const int d = d0 + ty + i * 8;
        g_xT[((size_t)b * Dd + d) * Seq + t0 + tx] = __fdiv_rn(tile[tx][ty + i * 8], rn);
    }
}

// ---------------- Kernel B2: emulate jax associative_scan cumsum + window ----------------
__global__ __launch_bounds__(256) void scan_kernel()
{
    constexpr int NLV = 12;
    constexpr int LLEN[NLV] = {2050,1025,512,256,128,64,32,16,8,4,2,1};
    constexpr int LOFF[NLV] = {0,2050,3075,3587,3843,3971,4035,4067,4083,4091,4095,4097};

    __shared__ float sm[2 * ROWBUF];
    const int tid = threadIdx.x;
    const size_t grow0 = (size_t)blockIdx.x * 2;

    for (int idx = tid; idx < 2 * Seq; idx += 256) {
        const int r = idx >> 11, t = idx & (Seq - 1);
        sm[r * ROWBUF + 2 + t] = g_xT[(grow0 + r) * Seq + t];
    }
    __syncthreads();
    if (tid < 2) {
        const float v = sm[tid * ROWBUF + 2];
        sm[tid * ROWBUF + 0] = v;
        sm[tid * ROWBUF + 1] = v;
    }
    __syncthreads();

#pragma unroll
    for (int L = 0; L < NLV - 1; ++L) {
        const int np = LLEN[L + 1];
        for (int idx = tid; idx < 2 * np; idx += 256) {
            const int r = (idx < np) ? 0 : 1;
            const int i = idx - r * np;
            float* base = sm + r * ROWBUF;
            base[LOFF[L + 1] + i] = base[LOFF[L] + 2 * i] + base[LOFF[L] + 2 * i + 1];
        }
        __syncthreads();
    }

#pragma unroll
    for (int L = NLV - 2; L >= 0; --L) {
        const int n    = LLEN[L];
        const int half = n >> 1;
        const int Ecnt = ((n + 1) >> 1) - 1;
        for (int idx = tid; idx < 2 * half; idx += 256) {
            const int r = (idx < half) ? 0 : 1;
            const int m = idx - r * half;
            float* base = sm + r * ROWBUF;
            const int me = m + 1;
            if (me <= Ecnt)
                base[LOFF[L] + 2 * me] += base[LOFF[L + 1] + me - 1];
            base[LOFF[L] + 2 * m + 1] = base[LOFF[L + 1] + m];
        }
        __syncthreads();
    }

    for (int idx = tid; idx < 2 * Seq; idx += 256) {
        const int r = idx >> 11, s = idx & (Seq - 1);
        const float* C = sm + r * ROWBUF;
        const float a  = C[s + 2];
        const float bs = (s >= 1) ? C[s - 1] : 0.0f;
        g_xT[(grow0 + r) * Seq + s] = __fdiv_rn(a - bs, 3.0f);
    }
}

// ---------------- Kernel C: split-K-parity GEMM, 8M x 8E per thread ----------------
// f32x2 lanes packed along E this round: B operand is natural (e,e+1) pairs from smem
// (no duplication -> half the B LDS bytes); X is loaded plain and duplicated into
// (x,x) registers via mov.b64 (ALU pipe, idle). 4 LDS.128 per 32 FMA2 vs previous 6.
// Per-output-element fma chain order unchanged -> bit-identical results.
__global__ __launch_bounds__(128) void gemm_kernel(const float* __restrict__ proto)
{
    __shared__ __align__(16) float  Xs[32][128];    // [k][m]  rows 512B
    __shared__ __align__(16) float2 Ps[32][34];     // [k][e-pair] plain pairs; rows 272B = 17*16

    const int tid = threadIdx.x;
    const int m0  = blockIdx.x * 128;
    const int par = blockIdx.y;
    const int b   = m0 >> 11;
    const int sl0 = m0 & (Seq - 1);
    const int tx  = tid & 7;             // experts tx*8 .. tx*8+7 (4 e-pairs)
    const int ty  = tid >> 3;            // tokens  ty*8 .. ty*8+7
    const int kr  = tid >> 5;            // X staging: base k row (0..3)
    const int m4  = (tid & 31) * 4;      // X staging: m offset

    unsigned long long acc[8][4];        // [token][e-pair]
#pragma unroll
    for (int i = 0; i < 8; ++i)
#pragma unroll
        for (int j = 0; j < 4; ++j) acc[i][j] = 0ull;

    // X stream base for this thread: rows kr+4j of each chunk, column m4
    const float* xbase = g_xT + ((size_t)(b * Dd + kr)) * Seq + sl0 + m4;

    // prefetch chunk ci=0 (k base = par*32)
    float4 xa[8];
#pragma unroll
    for (int j = 0; j < 8; ++j)
        xa[j] = *(const float4*)(xbase + ((size_t)(par * 32 + 4 * j)) * Seq);

    for (int ci = 0; ci < 16; ++ci) {
        const int ck = (2 * ci + par) * 32;   // current chunk k base
        __syncthreads();

        // stage prefetched X into smem
#pragma unroll
        for (int j = 0; j < 8; ++j)
            *(float4*)&Xs[kr + 4 * j][m4] = xa[j];

        // stage Ps: Ps[k][e>>1] = (proto[e][k], proto[e+1][k])  (plain pairs, no dup)
        for (int i = tid; i < 512; i += 128) {           // 4 iters
            const int e = i >> 3, k4 = (i & 7) * 4;
            const float4 pv = *(const float4*)&proto[(size_t)e * Dd + ck + k4];
            float* c0 = (float*)&Ps[k4 + 0][e >> 1] + (e & 1);
            float* c1 = (float*)&Ps[k4 + 1][e >> 1] + (e & 1);
            float* c2 = (float*)&Ps[k4 + 2][e >> 1] + (e & 1);
            float* c3 = (float*)&Ps[k4 + 3][e >> 1] + (e & 1);
            *c0 = pv.x;  *c1 = pv.y;  *c2 = pv.z;  *c3 = pv.w;
        }
        __syncthreads();

        // prefetch next chunk's X into registers (overlaps with FMA loop)
        if (ci + 1 < 16) {
            const int ckn = (2 * (ci + 1) + par) * 32;
#pragma unroll
            for (int j = 0; j < 8; ++j)
                xa[j] = *(const float4*)(xbase + ((size_t)(ckn + 4 * j)) * Seq);
        }

#pragma unroll
        for (int kk = 0; kk < 32; ++kk) {
            // X: 8 plain floats (2 LDS.128), duplicated into f32x2 in registers
            const float4 xv0 = *(const float4*)&Xs[kk][ty * 8];
            const float4 xv1 = *(const float4*)&Xs[kk][ty * 8 + 4];
            unsigned long long ap[8];
            DUP2(ap[0], xv0.x);  DUP2(ap[1], xv0.y);
            DUP2(ap[2], xv0.z);  DUP2(ap[3], xv0.w);
            DUP2(ap[4], xv1.x);  DUP2(ap[5], xv1.y);
            DUP2(ap[6], xv1.z);  DUP2(ap[7], xv1.w);
            // B: 4 natural (e,e+1) pairs (2 LDS.128)
            const ulonglong2 bq0 = *(const ulonglong2*)&Ps[kk][tx * 4];
            const ulonglong2 bq1 = *(const ulonglong2*)&Ps[kk][tx * 4 + 2];
            const unsigned long long bp[4] = {bq0.x, bq0.y, bq1.x, bq1.y};
#pragma unroll
            for (int mi = 0; mi < 8; ++mi)
#pragma unroll
                for (int ep = 0; ep < 4; ++ep)
                    FMA2(acc[mi][ep], ap[mi], bp[ep]);
        }
    }

    // write partial logits: acc[mi][ep] = experts (tx*8+2ep, tx*8+2ep+1) of token mbase+mi
    float* zp = g_zp[par];
    const int mbase = m0 + ty * 8;
#pragma unroll
    for (int mi = 0; mi < 8; ++mi) {
        union { unsigned long long u; float2 f; } c0, c1, c2, c3;
        c0.u = acc[mi][0];  c1.u = acc[mi][1];
        c2.u = acc[mi][2];  c3.u = acc[mi][3];
        const size_t r0 = ((size_t)(mbase + mi)) * Ee + tx * 8;
        *(float4*)&zp[r0]     = make_float4(c0.f.x, c0.f.y, c1.f.x, c1.f.y);
        *(float4*)&zp[r0 + 4] = make_float4(c2.f.x, c2.f.y, c3.f.x, c3.f.y);
    }
}

// ---------------- Kernel D: combine partials + softmax + top-2 ----------------
__global__ __launch_bounds__(256) void epilogue_kernel(float* __restrict__ out, int half)
{
    const int warp = (blockIdx.x * blockDim.x + threadIdx.x) >> 5;
    const int lane = threadIdx.x & 31;
    if (warp >= Mtot) return;
    const int t = warp;
    const int e0 = lane, e1 = lane + 32;

    // even + odd (same order as round-7's parity combine)
    const float l0 = g_zp[0][(size_t)t * Ee + e0] + g_zp[1][(size_t)t * Ee + e0];
    const float l1 = g_zp[0][(size_t)t * Ee + e1] + g_zp[1][(size_t)t * Ee + e1];

    // top-1 on logits (ties -> lower index, matching jax.lax.top_k)
    float bv = l0; int bi = e0;
    if (l1 > bv) { bv = l1; bi = e1; }
#pragma unroll
    for (int o = 16; o; o >>= 1) {
        const float ov = __shfl_xor_sync(FULLMASK, bv, o);
        const int   oi = __shfl_xor_sync(FULLMASK, bi, o);
        if (ov > bv || (ov == bv && oi < bi)) { bv = ov; bi = oi; }
    }
    const int i1 = bi; const float v1 = bv;     // also the row max

    // top-2
    float c0 = (e0 == i1) ? -FLT_MAX : l0;
    float c1 = (e1 == i1) ? -FLT_MAX : l1;
    bv = c0; bi = e0;
    if (c1 > bv) { bv = c1; bi = e1; }
#pragma unroll
    for (int o = 16; o; o >>= 1) {
        const float ov = __shfl_xor_sync(FULLMASK, bv, o);
        const int   oi = __shfl_xor_sync(FULLMASK, bi, o);
        if (ov > bv || (ov == bv && oi < bi)) { bv = ov; bi = oi; }
    }
    const int i2 = bi; const float v2 = bv;

    // softmax weights (fp32, max-shifted), renormalize the top-2 pair
    const float mx = v1;
    float sm = expf(l0 - mx) + expf(l1 - mx);
#pragma unroll
    for (int o = 16; o; o >>= 1) sm += __shfl_xor_sync(FULLMASK, sm, o);

    if (lane == 0) {
        const float p1 = __fdiv_rn(expf(v1 - mx), sm);
        const float p2 = __fdiv_rn(expf(v2 - mx), sm);
        const float den = p1 + p2;
        out[(size_t)t * 2 + 0] = (float)i1;
        out[(size_t)t * 2 + 1] = (float)i2;
        out[(size_t)half + (size_t)t * 2 + 0] = __fdiv_rn(p1, den);
        out[(size_t)half + (size_t)t * 2 + 1] = __fdiv_rn(p2, den);
    }
}

extern "C" void kernel_launch(void* const* d_in, const int* in_sizes, int n_in,
                              void* d_out, int out_size)
{
    const float* x = nullptr;
    const float* p = nullptr;
    for (int i = 0; i < n_in; ++i) {
        if (in_sizes[i] == Mtot * Dd)      x = (const float*)d_in[i];
        else if (in_sizes[i] == Ee * Dd)   p = (const float*)d_in[i];
    }

    norm_kernel<<<Mtot / 8, 256>>>(x);
    transpose_norm_kernel<<<dim3(Seq / 32, Dd / 32, Bb), dim3(32, 8)>>>(x);
    scan_kernel<<<Bb * Dd / 2, 256>>>();
    gemm_kernel<<<dim3(Mtot / 128, 2), 128>>>(p);

    float* out = (float*)d_out;
    const int half = out_size / 2;
    epilogue_kernel<<<(Mtot * 32 + 255) / 256, 256>>>(out, half);
}